// round 1
// baseline (speedup 1.0000x reference)
#include <cuda_runtime.h>

#define C_IN   64
#define C_OUT  128
#define HH     112
#define WW     112
#define BB     16
#define KH     3
#define KW     3
#define KTOT   (C_IN * KH * KW)   // 576

#define TH 16
#define TW 16
#define CIN_CHUNK 16
#define COUT_PER_BLK 32

// Scratch for masked weights (no cudaMalloc allowed)
__device__ float g_spw[C_OUT * KTOT];

__global__ void spw_kernel(const float* __restrict__ w, const float* __restrict__ m) {
    int i = blockIdx.x * blockDim.x + threadIdx.x;
    if (i < C_OUT * KTOT) g_spw[i] = w[i] * m[i];
}

__global__ __launch_bounds__(128)
void conv_kernel(const float* __restrict__ x, const float* __restrict__ bias,
                 float* __restrict__ out) {
    // input tile: CIN_CHUNK channels x (TH+2) x (TW+2), rows padded to 20 floats
    __shared__ float x_s[CIN_CHUNK][TH + 2][20];
    // weights transposed: [k_local][cout_local] -> warp-broadcast reads
    __shared__ float w_s[CIN_CHUNK * 9][COUT_PER_BLK];

    const int tid = threadIdx.x;
    const int w0  = blockIdx.x * TW;
    const int h0  = blockIdx.y * TH;
    const int b   = blockIdx.z >> 2;
    const int coutBase = (blockIdx.z & 3) * COUT_PER_BLK;

    const int cg   = tid >> 5;         // cout subgroup 0..3 (8 couts each)
    const int pxg  = tid & 31;         // pixel group 0..31
    const int row  = pxg >> 1;         // 0..15
    const int col0 = (pxg & 1) * 8;    // 0 or 8

    float acc[8][8];
    #pragma unroll
    for (int a = 0; a < 8; ++a)
        #pragma unroll
        for (int p = 0; p < 8; ++p) acc[a][p] = 0.f;

    for (int cin0 = 0; cin0 < C_IN; cin0 += CIN_CHUNK) {
        // ---- load input tile (zero-fill halo at image borders) ----
        for (int idx = tid; idx < CIN_CHUNK * 18 * 18; idx += 128) {
            int ci  = idx / (18 * 18);
            int rem = idx - ci * 324;
            int r = rem / 18;
            int c = rem - r * 18;
            int h = h0 - 1 + r;
            int w = w0 - 1 + c;
            float v = 0.f;
            if ((unsigned)h < HH && (unsigned)w < WW)
                v = x[(((b * C_IN) + cin0 + ci) * HH + h) * WW + w];
            x_s[ci][r][c] = v;
        }
        // ---- load masked weights for this (coutBase, cin0) slab ----
        for (int idx = tid; idx < CIN_CHUNK * 9 * COUT_PER_BLK; idx += 128) {
            int cl = idx & 31;
            int kl = idx >> 5;
            w_s[kl][cl] = g_spw[(coutBase + cl) * KTOT + cin0 * 9 + kl];
        }
        __syncthreads();

        // ---- compute: 8 couts x 8 pixels per thread ----
        for (int ci = 0; ci < CIN_CHUNK; ++ci) {
            #pragma unroll
            for (int i = 0; i < 3; ++i) {
                const float* xr = &x_s[ci][row + i][col0];
                float4 xa = *(const float4*)(xr);
                float4 xb = *(const float4*)(xr + 4);
                float2 xc = *(const float2*)(xr + 8);
                float xv[10] = {xa.x, xa.y, xa.z, xa.w,
                                xb.x, xb.y, xb.z, xb.w,
                                xc.x, xc.y};
                #pragma unroll
                for (int j = 0; j < 3; ++j) {
                    const float* wr = &w_s[ci * 9 + i * 3 + j][cg * 8];
                    float4 wa = *(const float4*)(wr);
                    float4 wb = *(const float4*)(wr + 4);
                    float wv[8] = {wa.x, wa.y, wa.z, wa.w,
                                   wb.x, wb.y, wb.z, wb.w};
                    #pragma unroll
                    for (int a = 0; a < 8; ++a)
                        #pragma unroll
                        for (int p = 0; p < 8; ++p)
                            acc[a][p] += wv[a] * xv[p + j];
                }
            }
        }
        __syncthreads();
    }

    // ---- epilogue: bias + aligned float4 stores ----
    #pragma unroll
    for (int a = 0; a < 8; ++a) {
        int cout = coutBase + cg * 8 + a;
        float bv = bias[cout];
        float* op = &out[(((b * C_OUT) + cout) * HH + (h0 + row)) * WW + w0 + col0];
        float4 o0 = {acc[a][0] + bv, acc[a][1] + bv, acc[a][2] + bv, acc[a][3] + bv};
        float4 o1 = {acc[a][4] + bv, acc[a][5] + bv, acc[a][6] + bv, acc[a][7] + bv};
        *(float4*)(op)     = o0;
        *(float4*)(op + 4) = o1;
    }
}

extern "C" void kernel_launch(void* const* d_in, const int* in_sizes, int n_in,
                              void* d_out, int out_size) {
    const float* x      = (const float*)d_in[0];
    const float* weight = (const float*)d_in[1];
    const float* mask   = (const float*)d_in[2];
    const float* bias   = (const float*)d_in[3];
    float* out = (float*)d_out;

    spw_kernel<<<(C_OUT * KTOT + 255) / 256, 256>>>(weight, mask);

    dim3 grid(WW / TW, HH / TH, BB * (C_OUT / COUT_PER_BLK));  // 7 x 7 x 64
    conv_kernel<<<grid, 128>>>(x, bias, out);
}

// round 5
// speedup vs baseline: 2.7722x; 2.7722x over previous
#include <cuda_runtime.h>
#include <cuda_fp16.h>
#include <cstdint>

#define NPIX   12544            // 112*112
#define CIN    64
#define COUT   128
#define KTOT   576
#define IMG_W  112
#define NTILE  128              // pixels per CTA
#define KCH    32               // K chunk
#define NCH    18               // 576/32
#define STR    40               // smem row stride in halves (80B)

// permuted-K slot -> source k (within a 16-block): slots {4q+r} hold
// k = 2q+r (r<2) or 2q+8+(r-2). Lets {b0,b1}/{a0,a2} be one LDS.64.
__host__ __device__ __forceinline__ int ksrc_of_slot(int j) {
    int blk = j & ~15, s = j & 15, q = s >> 2, r = s & 3;
    return blk + ((r < 2) ? (2 * q + r) : (2 * q + r + 6));
}

// masked weights, fp16, K-permuted
__device__ __half g_spw_h[COUT * KTOT];

__global__ void spw_kernel(const float* __restrict__ w, const float* __restrict__ m) {
    int i = blockIdx.x * blockDim.x + threadIdx.x;
    if (i < COUT * KTOT) {
        int row = i / KTOT, j = i - row * KTOT;
        int src = row * KTOT + ksrc_of_slot(j);
        g_spw_h[i] = __float2half_rn(w[src] * m[src]);
    }
}

__device__ __forceinline__ void mma16816(float* c, uint32_t a0, uint32_t a1,
                                         uint32_t a2, uint32_t a3,
                                         uint32_t b0, uint32_t b1) {
    asm volatile(
        "mma.sync.aligned.m16n8k16.row.col.f32.f16.f16.f32 "
        "{%0,%1,%2,%3},{%4,%5,%6,%7},{%8,%9},{%0,%1,%2,%3};"
        : "+f"(c[0]), "+f"(c[1]), "+f"(c[2]), "+f"(c[3])
        : "r"(a0), "r"(a1), "r"(a2), "r"(a3), "r"(b0), "r"(b1));
}

__global__ __launch_bounds__(512)
void conv_mma(const float* __restrict__ x, const float* __restrict__ bias,
              float* __restrict__ out) {
    // static smem: 4 * 10240B buffers + ktab = 43264B < 48KB
    __shared__ __align__(16) __half As[2][NTILE * STR];
    __shared__ __align__(16) __half Bs[2][NTILE * STR];
    __shared__ int ktab[KTOT];

    const int tid  = threadIdx.x;
    const int lane = tid & 31;
    const int wid  = tid >> 5;          // 0..15
    const int wm   = wid & 3;           // warp m-tile (32 couts)
    const int wn   = wid >> 2;          // warp n-tile (32 pixels)
    const int g    = lane >> 2;         // group 0..7
    const int tig  = lane & 3;

    // ---- ktab: permuted slot -> packed (gmem offset, k%9) ----
    for (int j = tid; j < KTOT; j += 512) {
        int k = ksrc_of_slot(j);
        int ci = k / 9, rem = k - ci * 9;
        int rr = rem / 3, jj = rem - rr * 3;
        int off = ci * NPIX + (rr - 1) * IMG_W + (jj - 1);
        ktab[j] = (off << 4) | rem;
    }

    // ---- geometry ----
    const int bi = blockIdx.x;
    const int b  = bi / 98;                      // 12544/128 = 98 tiles/image
    const int m0 = (bi - b * 98) * NTILE;
    const float* xb = x + (size_t)b * CIN * NPIX;

    // B-fill role: pixel p, eighth kq (8 k-slots); A-fill: row am, slots akq*8
    const int p    = tid & 127;
    const int kq   = tid >> 7;                   // 0..3
    const int gpix = m0 + p;
    const int ph   = gpix / IMG_W;
    const int pw   = gpix - ph * IMG_W;
    unsigned vm = 0;
    #pragma unroll
    for (int rr = 0; rr < 3; ++rr)
        #pragma unroll
        for (int jj = 0; jj < 3; ++jj)
            if ((unsigned)(ph + rr - 1) < (unsigned)IMG_W &&
                (unsigned)(pw + jj - 1) < (unsigned)IMG_W)
                vm |= 1u << (rr * 3 + jj);

    const int am  = tid >> 2;
    const int akq = tid & 3;

    __syncthreads();   // ktab ready

    float c[2][4][4];
    #pragma unroll
    for (int mt = 0; mt < 2; ++mt)
        #pragma unroll
        for (int nt = 0; nt < 4; ++nt)
            #pragma unroll
            for (int i = 0; i < 4; ++i) c[mt][nt][i] = 0.f;

    // ---- prologue: fill buf 0 (chunk 0) ----
    {
        const uint4 av = *(const uint4*)(g_spw_h + am * KTOT + akq * 8);
        float gv[8];
        #pragma unroll
        for (int i = 0; i < 8; ++i) {
            int pk = ktab[kq * 8 + i];
            gv[i] = ((vm >> (pk & 15)) & 1u) ? __ldg(xb + gpix + (pk >> 4)) : 0.f;
        }
        *(uint4*)(As[0] + am * STR + akq * 8) = av;
        uint32_t hp[4];
        #pragma unroll
        for (int i = 0; i < 4; ++i) {
            __half2 h = __floats2half2_rn(gv[2 * i], gv[2 * i + 1]);
            hp[i] = *(uint32_t*)&h;
        }
        *(uint4*)(Bs[0] + p * STR + kq * 8) = make_uint4(hp[0], hp[1], hp[2], hp[3]);
    }
    __syncthreads();

    // ---- mainloop ----
    for (int t = 0; t < NCH; ++t) {
        const int cur = t & 1;
        const bool hasNext = (t + 1) < NCH;

        // prefetch next chunk (LDG only; STS after mma)
        uint4 av;
        float gv[8];
        if (hasNext) {
            const int k0 = (t + 1) * KCH;
            av = *(const uint4*)(g_spw_h + am * KTOT + k0 + akq * 8);
            #pragma unroll
            for (int i = 0; i < 8; ++i) {
                int pk = ktab[k0 + kq * 8 + i];
                gv[i] = ((vm >> (pk & 15)) & 1u) ? __ldg(xb + gpix + (pk >> 4)) : 0.f;
            }
        }

        // mma over current buffer: 2 k-steps of 16
        const __half* A = As[cur];
        const __half* B = Bs[cur];
        #pragma unroll
        for (int ks = 0; ks < 2; ++ks) {
            uint32_t a[2][4];
            #pragma unroll
            for (int mt = 0; mt < 2; ++mt) {
                int row = wm * 32 + mt * 16;
                uint2 lo = *(const uint2*)(A + (row + g) * STR + ks * 16 + tig * 4);
                uint2 hi = *(const uint2*)(A + (row + g + 8) * STR + ks * 16 + tig * 4);
                a[mt][0] = lo.x; a[mt][2] = lo.y;   // a0, a2
                a[mt][1] = hi.x; a[mt][3] = hi.y;   // a1, a3
            }
            uint32_t bf[4][2];
            #pragma unroll
            for (int nt = 0; nt < 4; ++nt) {
                uint2 v = *(const uint2*)(B + (wn * 32 + nt * 8 + g) * STR + ks * 16 + tig * 4);
                bf[nt][0] = v.x; bf[nt][1] = v.y;   // b0, b1
            }
            #pragma unroll
            for (int mt = 0; mt < 2; ++mt)
                #pragma unroll
                for (int nt = 0; nt < 4; ++nt)
                    mma16816(c[mt][nt], a[mt][0], a[mt][1], a[mt][2], a[mt][3],
                             bf[nt][0], bf[nt][1]);
        }

        // store next chunk
        if (hasNext) {
            const int nxt = cur ^ 1;
            *(uint4*)(As[nxt] + am * STR + akq * 8) = av;
            uint32_t hp[4];
            #pragma unroll
            for (int i = 0; i < 4; ++i) {
                __half2 h = __floats2half2_rn(gv[2 * i], gv[2 * i + 1]);
                hp[i] = *(uint32_t*)&h;
            }
            *(uint4*)(Bs[nxt] + p * STR + kq * 8) = make_uint4(hp[0], hp[1], hp[2], hp[3]);
        }
        __syncthreads();
    }

    // ---- epilogue: bias + direct fragment stores ----
    #pragma unroll
    for (int mt = 0; mt < 2; ++mt) {
        const int r0 = wm * 32 + mt * 16 + g;
        const float bv0 = __ldg(bias + r0);
        const float bv1 = __ldg(bias + r0 + 8);
        float* o0 = out + ((size_t)(b * COUT + r0)) * NPIX + m0;
        float* o1 = out + ((size_t)(b * COUT + r0 + 8)) * NPIX + m0;
        #pragma unroll
        for (int nt = 0; nt < 4; ++nt) {
            const int col = wn * 32 + nt * 8 + tig * 2;
            float2 v0 = { c[mt][nt][0] + bv0, c[mt][nt][1] + bv0 };
            float2 v1 = { c[mt][nt][2] + bv1, c[mt][nt][3] + bv1 };
            *(float2*)(o0 + col) = v0;
            *(float2*)(o1 + col) = v1;
        }
    }
}

extern "C" void kernel_launch(void* const* d_in, const int* in_sizes, int n_in,
                              void* d_out, int out_size) {
    const float* x      = (const float*)d_in[0];
    const float* weight = (const float*)d_in[1];
    const float* mask   = (const float*)d_in[2];
    const float* bias   = (const float*)d_in[3];
    float* out = (float*)d_out;

    spw_kernel<<<(COUT * KTOT + 255) / 256, 256>>>(weight, mask);
    conv_mma<<<16 * (NPIX / NTILE), 512>>>(x, bias, out);
}

// round 7
// speedup vs baseline: 3.9002x; 1.4069x over previous
#include <cuda_runtime.h>
#include <cuda_fp16.h>
#include <cstdint>

#define NPIX  12544
#define CIN   64
#define COUT  128
#define KTOT  576
#define IMG_W 112
#define BB    16
#define NTILE 128
#define KCH   48
#define NCH   12            // 576/48
#define STRH  48            // halves per smem row
#define ROWB  96            // bytes per smem row

// ---- device globals (no allocs allowed) ----
__device__ __half g_xh[BB * CIN * NPIX];           // fp16 copy of x (~24.5MB)
__device__ __half g_spw2[NCH * COUT * STRH];       // weights, chunk-major, col-swizzled
__device__ int    g_ktab[KTOT];                    // (gmem_off<<4) | (k%9)

// ---- pre-kernels ----
__global__ void x2h_kernel(const float* __restrict__ x) {
    int i = blockIdx.x * blockDim.x + threadIdx.x;   // group of 8 floats
    const float4* src = (const float4*)x + (size_t)i * 2;
    float4 a = src[0], b = src[1];
    __half2 h0 = __floats2half2_rn(a.x, a.y);
    __half2 h1 = __floats2half2_rn(a.z, a.w);
    __half2 h2 = __floats2half2_rn(b.x, b.y);
    __half2 h3 = __floats2half2_rn(b.z, b.w);
    uint4 o = { *(uint32_t*)&h0, *(uint32_t*)&h1, *(uint32_t*)&h2, *(uint32_t*)&h3 };
    ((uint4*)g_xh)[i] = o;
}

__global__ void spw2_kernel(const float* __restrict__ w, const float* __restrict__ m) {
    int i = blockIdx.x * blockDim.x + threadIdx.x;
    if (i < NCH * COUT * STRH) {
        int t = i / (COUT * STRH);
        int rem = i - t * (COUT * STRH);
        int r = rem / STRH;
        int s = rem - r * STRH;
        int k = t * KCH + (s ^ ((r & 4) ? 8 : 0));   // bake 16B-block swizzle
        g_spw2[i] = __float2half_rn(w[r * KTOT + k] * m[r * KTOT + k]);
    }
    if (i < KTOT) {
        int ci = i / 9, rm = i - ci * 9;
        int rr = rm / 3, jj = rm - rr * 3;
        int off = ci * NPIX + (rr - 1) * IMG_W + (jj - 1);
        g_ktab[i] = (off << 4) | rm;
    }
}

// ---- asm helpers ----
__device__ __forceinline__ uint32_t smem_u32(const void* p) {
    uint32_t a;
    asm("{ .reg .u64 t; cvta.to.shared.u64 t, %1; cvt.u32.u64 %0, t; }" : "=r"(a) : "l"(p));
    return a;
}
__device__ __forceinline__ void cpasync16(uint32_t dst, const void* src) {
    asm volatile("cp.async.cg.shared.global [%0], [%1], 16;" :: "r"(dst), "l"(src));
}
__device__ __forceinline__ void ldsm_x4(uint32_t& r0, uint32_t& r1, uint32_t& r2,
                                        uint32_t& r3, uint32_t addr) {
    asm volatile("ldmatrix.sync.aligned.m8n8.x4.shared.b16 {%0,%1,%2,%3}, [%4];"
                 : "=r"(r0), "=r"(r1), "=r"(r2), "=r"(r3) : "r"(addr));
}
__device__ __forceinline__ void mma16816(float* c, uint32_t a0, uint32_t a1,
                                         uint32_t a2, uint32_t a3,
                                         uint32_t b0, uint32_t b1) {
    asm volatile(
        "mma.sync.aligned.m16n8k16.row.col.f32.f16.f16.f32 "
        "{%0,%1,%2,%3},{%4,%5,%6,%7},{%8,%9},{%0,%1,%2,%3};"
        : "+f"(c[0]), "+f"(c[1]), "+f"(c[2]), "+f"(c[3])
        : "r"(a0), "r"(a1), "r"(a2), "r"(a3), "r"(b0), "r"(b1));
}

// ---- main kernel ----
__global__ __launch_bounds__(256, 2)
void conv_mma(const float* __restrict__ bias, float* __restrict__ out) {
    __shared__ __align__(16) __half As[2][COUT * STRH];   // 2 x 12288B
    __shared__ __align__(16) __half Bs[2][NTILE * STRH];  // 2 x 12288B  (total 48KB)

    const int tid  = threadIdx.x;
    const int lane = tid & 31;
    const int wid  = tid >> 5;           // 0..7
    const int wm   = wid & 3;            // 32-cout tile
    const int wn   = wid >> 2;           // 64-pixel tile
    const int g    = lane >> 2;
    const int tig  = lane & 3;

    const uint32_t sA[2] = { smem_u32(&As[0][0]), smem_u32(&As[1][0]) };
    const uint32_t sB[2] = { smem_u32(&Bs[0][0]), smem_u32(&Bs[1][0]) };

    // ldmatrix per-lane bases (swizzle bit constant per lane)
    const int a_row = wm * 32 + ((lane >> 3) & 1) * 8 + (lane & 7);
    const int a_cb  = lane >> 4;                     // 0/1 k-subblock
    const int a_swz = (a_row & 4) ? 1 : 0;
    const int b_row = wn * 64 + (lane >> 4) * 8 + (lane & 7);
    const int b_cb  = (lane >> 3) & 1;
    const int b_swz = (b_row & 4) ? 1 : 0;

    // geometry
    const int bi = blockIdx.x;
    const int b  = bi / 98;
    const int m0 = (bi - b * 98) * NTILE;
    const __half* xb = g_xh + (size_t)b * CIN * NPIX;

    // fill roles: p = pixel, kh = half-row (24 halves)
    const int p  = tid >> 1;
    const int kh = tid & 1;
    const int gpix = m0 + p;
    const int ph = gpix / IMG_W;
    const int pw = gpix - ph * IMG_W;
    unsigned vm = 0;
    #pragma unroll
    for (int rr = 0; rr < 3; ++rr)
        #pragma unroll
        for (int jj = 0; jj < 3; ++jj)
            if ((unsigned)(ph + rr - 1) < (unsigned)IMG_W &&
                (unsigned)(pw + jj - 1) < (unsigned)IMG_W)
                vm |= 1u << (rr * 3 + jj);
    const int bswz = (p & 4) ? 1 : 0;

    float c[2][8][4];
    #pragma unroll
    for (int mt = 0; mt < 2; ++mt)
        #pragma unroll
        for (int nt = 0; nt < 8; ++nt)
            #pragma unroll
            for (int i = 0; i < 4; ++i) c[mt][nt][i] = 0.f;

    // ---- prologue: fill buf 0 ----
    {
        const __half* asrc = g_spw2 + tid * 24;
        uint32_t adst = sA[0] + tid * 48;
        cpasync16(adst, asrc);
        cpasync16(adst + 16, asrc + 8);
        cpasync16(adst + 32, asrc + 16);
        asm volatile("cp.async.commit_group;" ::: "memory");

        uint32_t bpack[12];
        const int kb = kh * 24;
        #pragma unroll
        for (int j = 0; j < 12; ++j) {
            int pk0 = g_ktab[kb + 2 * j], pk1 = g_ktab[kb + 2 * j + 1];
            __half v0 = __ushort_as_half((unsigned short)0), v1 = v0;
            if ((vm >> (pk0 & 15)) & 1u) v0 = xb[gpix + (pk0 >> 4)];
            if ((vm >> (pk1 & 15)) & 1u) v1 = xb[gpix + (pk1 >> 4)];
            __half2 hh = __halves2half2(v0, v1);
            bpack[j] = *(uint32_t*)&hh;
        }
        char* rowp = (char*)&Bs[0][0] + p * ROWB;
        #pragma unroll
        for (int j = 0; j < 3; ++j) {
            int bb = kh * 3 + j;
            *(uint4*)(rowp + ((bb ^ bswz) * 16)) =
                make_uint4(bpack[4 * j], bpack[4 * j + 1], bpack[4 * j + 2], bpack[4 * j + 3]);
        }
        asm volatile("cp.async.wait_group 0;" ::: "memory");
    }
    __syncthreads();

    // ---- mainloop ----
    for (int t = 0; t < NCH; ++t) {
        const int cur = t & 1;
        const int nxt = cur ^ 1;
        const bool hasNext = (t + 1) < NCH;

        uint32_t bpack[12];
        if (hasNext) {
            const __half* asrc = g_spw2 + (size_t)(t + 1) * (COUT * STRH) + tid * 24;
            uint32_t adst = sA[nxt] + tid * 48;
            cpasync16(adst, asrc);
            cpasync16(adst + 16, asrc + 8);
            cpasync16(adst + 32, asrc + 16);
            asm volatile("cp.async.commit_group;" ::: "memory");

            const int kb = (t + 1) * KCH + kh * 24;
            #pragma unroll
            for (int j = 0; j < 12; ++j) {
                int pk0 = g_ktab[kb + 2 * j], pk1 = g_ktab[kb + 2 * j + 1];
                __half v0 = __ushort_as_half((unsigned short)0), v1 = v0;
                if ((vm >> (pk0 & 15)) & 1u) v0 = xb[gpix + (pk0 >> 4)];
                if ((vm >> (pk1 & 15)) & 1u) v1 = xb[gpix + (pk1 >> 4)];
                __half2 hh = __halves2half2(v0, v1);
                bpack[j] = *(uint32_t*)&hh;
            }
        }

        // mma: 3 k-steps of 16
        #pragma unroll
        for (int ks = 0; ks < 3; ++ks) {
            uint32_t a[2][4];
            #pragma unroll
            for (int mt = 0; mt < 2; ++mt)
                ldsm_x4(a[mt][0], a[mt][1], a[mt][2], a[mt][3],
                        sA[cur] + (a_row + mt * 16) * ROWB + (((ks * 2 + a_cb) ^ a_swz) * 16));
            #pragma unroll
            for (int ntp = 0; ntp < 4; ++ntp) {
                uint32_t b0, b1, b2, b3;
                ldsm_x4(b0, b1, b2, b3,
                        sB[cur] + (b_row + ntp * 16) * ROWB + (((ks * 2 + b_cb) ^ b_swz) * 16));
                #pragma unroll
                for (int mt = 0; mt < 2; ++mt) {
                    mma16816(c[mt][2 * ntp],     a[mt][0], a[mt][1], a[mt][2], a[mt][3], b0, b1);
                    mma16816(c[mt][2 * ntp + 1], a[mt][0], a[mt][1], a[mt][2], a[mt][3], b2, b3);
                }
            }
        }

        if (hasNext) {
            char* rowp = (char*)&Bs[nxt][0] + p * ROWB;
            #pragma unroll
            for (int j = 0; j < 3; ++j) {
                int bb = kh * 3 + j;
                *(uint4*)(rowp + ((bb ^ bswz) * 16)) =
                    make_uint4(bpack[4 * j], bpack[4 * j + 1], bpack[4 * j + 2], bpack[4 * j + 3]);
            }
        }
        asm volatile("cp.async.wait_group 0;" ::: "memory");
        __syncthreads();
    }

    // ---- epilogue ----
    #pragma unroll
    for (int mt = 0; mt < 2; ++mt) {
        const int r0 = wm * 32 + mt * 16 + g;
        const float bv0 = __ldg(bias + r0);
        const float bv1 = __ldg(bias + r0 + 8);
        float* o0 = out + ((size_t)(b * COUT + r0)) * NPIX + m0;
        float* o1 = out + ((size_t)(b * COUT + r0 + 8)) * NPIX + m0;
        #pragma unroll
        for (int nt = 0; nt < 8; ++nt) {
            const int col = wn * 64 + nt * 8 + tig * 2;
            float2 v0 = { c[mt][nt][0] + bv0, c[mt][nt][1] + bv0 };
            float2 v1 = { c[mt][nt][2] + bv1, c[mt][nt][3] + bv1 };
            *(float2*)(o0 + col) = v0;
            *(float2*)(o1 + col) = v1;
        }
    }
}

extern "C" void kernel_launch(void* const* d_in, const int* in_sizes, int n_in,
                              void* d_out, int out_size) {
    const float* x      = (const float*)d_in[0];
    const float* weight = (const float*)d_in[1];
    const float* mask   = (const float*)d_in[2];
    const float* bias   = (const float*)d_in[3];
    float* out = (float*)d_out;

    x2h_kernel<<<(BB * CIN * NPIX / 8) / 256, 256>>>(x);
    spw2_kernel<<<(NCH * COUT * STRH + 255) / 256, 256>>>(weight, mask);
    conv_mma<<<BB * (NPIX / NTILE), 256>>>(bias, out);
}

// round 9
// speedup vs baseline: 3.9489x; 1.0125x over previous
#include <cuda_runtime.h>
#include <cuda_fp16.h>
#include <cstdint>

#define NPIX  12544
#define CIN   64
#define COUT  128
#define KTOT  576
#define IMG_W 112
#define BB    16
#define NTILE 128
#define KCH   48
#define NCH   12            // 576/48
#define STRH  48            // halves per smem row
#define ROWB  96            // bytes per smem row

// ---- device globals (no allocs allowed) ----
__device__ __half g_spw2[NCH * COUT * STRH];       // weights, chunk-major, col-swizzled
__device__ int    g_ktab[KTOT];                    // (gmem_off<<4) | (k%9)

// ---- pre-kernel: masked fp16 weights + k-offset table ----
__global__ void spw2_kernel(const float* __restrict__ w, const float* __restrict__ m) {
    int i = blockIdx.x * blockDim.x + threadIdx.x;
    if (i < NCH * COUT * STRH) {
        int t = i / (COUT * STRH);
        int rem = i - t * (COUT * STRH);
        int r = rem / STRH;
        int s = rem - r * STRH;
        int k = t * KCH + (s ^ ((r & 4) ? 8 : 0));   // bake 16B-block swizzle
        g_spw2[i] = __float2half_rn(w[r * KTOT + k] * m[r * KTOT + k]);
    }
    if (i < KTOT) {
        int ci = i / 9, rm = i - ci * 9;
        int rr = rm / 3, jj = rm - rr * 3;
        int off = ci * NPIX + (rr - 1) * IMG_W + (jj - 1);
        g_ktab[i] = (off << 4) | rm;
    }
}

// ---- asm helpers ----
__device__ __forceinline__ uint32_t smem_u32(const void* p) {
    uint32_t a;
    asm("{ .reg .u64 t; cvta.to.shared.u64 t, %1; cvt.u32.u64 %0, t; }" : "=r"(a) : "l"(p));
    return a;
}
__device__ __forceinline__ void cpasync16(uint32_t dst, const void* src) {
    asm volatile("cp.async.cg.shared.global [%0], [%1], 16;" :: "r"(dst), "l"(src));
}
__device__ __forceinline__ void ldsm_x4(uint32_t& r0, uint32_t& r1, uint32_t& r2,
                                        uint32_t& r3, uint32_t addr) {
    asm volatile("ldmatrix.sync.aligned.m8n8.x4.shared.b16 {%0,%1,%2,%3}, [%4];"
                 : "=r"(r0), "=r"(r1), "=r"(r2), "=r"(r3) : "r"(addr));
}
__device__ __forceinline__ void mma16816(float* c, uint32_t a0, uint32_t a1,
                                         uint32_t a2, uint32_t a3,
                                         uint32_t b0, uint32_t b1) {
    asm volatile(
        "mma.sync.aligned.m16n8k16.row.col.f32.f16.f16.f32 "
        "{%0,%1,%2,%3},{%4,%5,%6,%7},{%8,%9},{%0,%1,%2,%3};"
        : "+f"(c[0]), "+f"(c[1]), "+f"(c[2]), "+f"(c[3])
        : "r"(a0), "r"(a1), "r"(a2), "r"(a3), "r"(b0), "r"(b1));
}

// ---- main kernel ----
__global__ __launch_bounds__(256, 2)
void conv_mma(const float* __restrict__ x, const float* __restrict__ bias,
              float* __restrict__ out) {
    __shared__ __align__(16) __half As[2][COUT * STRH];   // 2 x 12288B
    __shared__ __align__(16) __half Bs[2][NTILE * STRH];  // 2 x 12288B  (total 48KB)

    const int tid  = threadIdx.x;
    const int lane = tid & 31;
    const int wid  = tid >> 5;           // 0..7
    const int wm   = wid & 3;            // 32-cout tile
    const int wn   = wid >> 2;           // 64-pixel tile
    const int g    = lane >> 2;
    const int tig  = lane & 3;

    const uint32_t sA[2] = { smem_u32(&As[0][0]), smem_u32(&As[1][0]) };
    const uint32_t sB[2] = { smem_u32(&Bs[0][0]), smem_u32(&Bs[1][0]) };

    // ldmatrix per-lane bases (swizzle bit constant per lane)
    const int a_row = wm * 32 + ((lane >> 3) & 1) * 8 + (lane & 7);
    const int a_cb  = lane >> 4;                     // 0/1 k-subblock
    const int a_swz = (a_row & 4) ? 1 : 0;
    const int b_row = wn * 64 + (lane >> 4) * 8 + (lane & 7);
    const int b_cb  = (lane >> 3) & 1;
    const int b_swz = (b_row & 4) ? 1 : 0;

    // geometry
    const int bi = blockIdx.x;
    const int b  = bi / 98;
    const int m0 = (bi - b * 98) * NTILE;
    const float* xb = x + (size_t)b * CIN * NPIX;

    // fill roles: p = pixel, kh = half-row (24 halves)
    const int p  = tid >> 1;
    const int kh = tid & 1;
    const int gpix = m0 + p;
    const int ph = gpix / IMG_W;
    const int pw = gpix - ph * IMG_W;
    unsigned vm = 0;
    #pragma unroll
    for (int rr = 0; rr < 3; ++rr)
        #pragma unroll
        for (int jj = 0; jj < 3; ++jj)
            if ((unsigned)(ph + rr - 1) < (unsigned)IMG_W &&
                (unsigned)(pw + jj - 1) < (unsigned)IMG_W)
                vm |= 1u << (rr * 3 + jj);
    const int bswz = (p & 4) ? 1 : 0;

    float c[2][8][4];
    #pragma unroll
    for (int mt = 0; mt < 2; ++mt)
        #pragma unroll
        for (int nt = 0; nt < 8; ++nt)
            #pragma unroll
            for (int i = 0; i < 4; ++i) c[mt][nt][i] = 0.f;

    // ---- prologue: fill buf 0 ----
    {
        const __half* asrc = g_spw2 + tid * 24;
        uint32_t adst = sA[0] + tid * 48;
        cpasync16(adst, asrc);
        cpasync16(adst + 16, asrc + 8);
        cpasync16(adst + 32, asrc + 16);
        asm volatile("cp.async.commit_group;" ::: "memory");

        uint32_t bpack[12];
        const int kb = kh * 24;
        #pragma unroll
        for (int j = 0; j < 12; ++j) {
            int pk0 = g_ktab[kb + 2 * j], pk1 = g_ktab[kb + 2 * j + 1];
            float v0 = 0.f, v1 = 0.f;
            if ((vm >> (pk0 & 15)) & 1u) v0 = __ldg(xb + gpix + (pk0 >> 4));
            if ((vm >> (pk1 & 15)) & 1u) v1 = __ldg(xb + gpix + (pk1 >> 4));
            __half2 hh = __floats2half2_rn(v0, v1);
            bpack[j] = *(uint32_t*)&hh;
        }
        char* rowp = (char*)&Bs[0][0] + p * ROWB;
        #pragma unroll
        for (int j = 0; j < 3; ++j) {
            int bb = kh * 3 + j;
            *(uint4*)(rowp + ((bb ^ bswz) * 16)) =
                make_uint4(bpack[4 * j], bpack[4 * j + 1], bpack[4 * j + 2], bpack[4 * j + 3]);
        }
        asm volatile("cp.async.wait_group 0;" ::: "memory");
    }
    __syncthreads();

    // ---- mainloop ----
    for (int t = 0; t < NCH; ++t) {
        const int cur = t & 1;
        const int nxt = cur ^ 1;
        const bool hasNext = (t + 1) < NCH;

        uint32_t bpack[12];
        if (hasNext) {
            const __half* asrc = g_spw2 + (size_t)(t + 1) * (COUT * STRH) + tid * 24;
            uint32_t adst = sA[nxt] + tid * 48;
            cpasync16(adst, asrc);
            cpasync16(adst + 16, asrc + 8);
            cpasync16(adst + 32, asrc + 16);
            asm volatile("cp.async.commit_group;" ::: "memory");

            const int kb = (t + 1) * KCH + kh * 24;
            #pragma unroll
            for (int j = 0; j < 12; ++j) {
                int pk0 = g_ktab[kb + 2 * j], pk1 = g_ktab[kb + 2 * j + 1];
                float v0 = 0.f, v1 = 0.f;
                if ((vm >> (pk0 & 15)) & 1u) v0 = __ldg(xb + gpix + (pk0 >> 4));
                if ((vm >> (pk1 & 15)) & 1u) v1 = __ldg(xb + gpix + (pk1 >> 4));
                __half2 hh = __floats2half2_rn(v0, v1);
                bpack[j] = *(uint32_t*)&hh;
            }
        }

        // mma: 3 k-steps of 16
        #pragma unroll
        for (int ks = 0; ks < 3; ++ks) {
            uint32_t a[2][4];
            #pragma unroll
            for (int mt = 0; mt < 2; ++mt)
                ldsm_x4(a[mt][0], a[mt][1], a[mt][2], a[mt][3],
                        sA[cur] + (a_row + mt * 16) * ROWB + (((ks * 2 + a_cb) ^ a_swz) * 16));
            #pragma unroll
            for (int ntp = 0; ntp < 4; ++ntp) {
                uint32_t b0, b1, b2, b3;
                ldsm_x4(b0, b1, b2, b3,
                        sB[cur] + (b_row + ntp * 16) * ROWB + (((ks * 2 + b_cb) ^ b_swz) * 16));
                #pragma unroll
                for (int mt = 0; mt < 2; ++mt) {
                    mma16816(c[mt][2 * ntp],     a[mt][0], a[mt][1], a[mt][2], a[mt][3], b0, b1);
                    mma16816(c[mt][2 * ntp + 1], a[mt][0], a[mt][1], a[mt][2], a[mt][3], b2, b3);
                }
            }
        }

        if (hasNext) {
            char* rowp = (char*)&Bs[nxt][0] + p * ROWB;
            #pragma unroll
            for (int j = 0; j < 3; ++j) {
                int bb = kh * 3 + j;
                *(uint4*)(rowp + ((bb ^ bswz) * 16)) =
                    make_uint4(bpack[4 * j], bpack[4 * j + 1], bpack[4 * j + 2], bpack[4 * j + 3]);
            }
        }
        asm volatile("cp.async.wait_group 0;" ::: "memory");
        __syncthreads();
    }

    // ---- epilogue ----
    #pragma unroll
    for (int mt = 0; mt < 2; ++mt) {
        const int r0 = wm * 32 + mt * 16 + g;
        const float bv0 = __ldg(bias + r0);
        const float bv1 = __ldg(bias + r0 + 8);
        float* o0 = out + ((size_t)(b * COUT + r0)) * NPIX + m0;
        float* o1 = out + ((size_t)(b * COUT + r0 + 8)) * NPIX + m0;
        #pragma unroll
        for (int nt = 0; nt < 8; ++nt) {
            const int col = wn * 64 + nt * 8 + tig * 2;
            float2 v0 = { c[mt][nt][0] + bv0, c[mt][nt][1] + bv0 };
            float2 v1 = { c[mt][nt][2] + bv1, c[mt][nt][3] + bv1 };
            *(float2*)(o0 + col) = v0;
            *(float2*)(o1 + col) = v1;
        }
    }
}

extern "C" void kernel_launch(void* const* d_in, const int* in_sizes, int n_in,
                              void* d_out, int out_size) {
    const float* x      = (const float*)d_in[0];
    const float* weight = (const float*)d_in[1];
    const float* mask   = (const float*)d_in[2];
    const float* bias   = (const float*)d_in[3];
    float* out = (float*)d_out;

    spw2_kernel<<<(NCH * COUT * STRH + 255) / 256, 256>>>(weight, mask);
    conv_mma<<<BB * (NPIX / NTILE), 256>>>(x, bias, out);
}

// round 12
// speedup vs baseline: 5.8143x; 1.4724x over previous
#include <cuda_runtime.h>
#include <cuda_fp16.h>
#include <cstdint>

#define NPIX  12544
#define CIN   64
#define COUT  128
#define KTOT  576
#define IMG_W 112
#define BB    16
#define NTILE 128
#define KCH   32            // one chunk = 32 channels of ONE kernel tap
#define NCH   18            // 576/32
#define ROWB  64            // bytes per smem row (32 halves)

// ---- device globals ----
// weights, chunk-major [NCH][COUT][KCH], tap-major K order, ldsm swizzle baked
__device__ __half g_spw2[NCH * COUT * KCH];

// ---- pre-kernel: masked fp16 weights in tap-major, swizzled layout ----
__global__ void spw2_kernel(const float* __restrict__ w, const float* __restrict__ m) {
    int i = blockIdx.x * blockDim.x + threadIdx.x;
    if (i < NCH * COUT * KCH) {
        int t   = i / (COUT * KCH);
        int rem = i - t * (COUT * KCH);
        int r   = rem / KCH;            // cout row
        int s   = rem - r * KCH;        // half position within 64B row
        int blk = s >> 3;               // 16B block 0..3
        int within = s & 7;
        int oblk = blk ^ ((r >> 1) & 3);          // undo read-side swizzle
        int kic  = oblk * 8 + within;             // k-in-chunk 0..31
        int rm   = t >> 1;                        // tap 0..8
        int ci   = (t & 1) * 32 + kic;            // channel 0..63
        int k    = ci * 9 + rm;                   // original K index
        g_spw2[i] = __float2half_rn(w[r * KTOT + k] * m[r * KTOT + k]);
    }
}

// ---- asm helpers ----
__device__ __forceinline__ uint32_t smem_u32(const void* p) {
    uint32_t a;
    asm("{ .reg .u64 t; cvta.to.shared.u64 t, %1; cvt.u32.u64 %0, t; }" : "=r"(a) : "l"(p));
    return a;
}
__device__ __forceinline__ void cpasync16(uint32_t dst, const void* src) {
    asm volatile("cp.async.cg.shared.global [%0], [%1], 16;" :: "r"(dst), "l"(src));
}
__device__ __forceinline__ void ldsm_x4(uint32_t& r0, uint32_t& r1, uint32_t& r2,
                                        uint32_t& r3, uint32_t addr) {
    asm volatile("ldmatrix.sync.aligned.m8n8.x4.shared.b16 {%0,%1,%2,%3}, [%4];"
                 : "=r"(r0), "=r"(r1), "=r"(r2), "=r"(r3) : "r"(addr));
}
__device__ __forceinline__ void mma16816(float* c, uint32_t a0, uint32_t a1,
                                         uint32_t a2, uint32_t a3,
                                         uint32_t b0, uint32_t b1) {
    asm volatile(
        "mma.sync.aligned.m16n8k16.row.col.f32.f16.f16.f32 "
        "{%0,%1,%2,%3},{%4,%5,%6,%7},{%8,%9},{%0,%1,%2,%3};"
        : "+f"(c[0]), "+f"(c[1]), "+f"(c[2]), "+f"(c[3])
        : "r"(a0), "r"(a1), "r"(a2), "r"(a3), "r"(b0), "r"(b1));
}

// ---- main kernel ----
__global__ __launch_bounds__(256, 2)
void conv_mma(const float* __restrict__ x, const float* __restrict__ bias,
              float* __restrict__ out) {
    __shared__ __align__(16) __half As[2][COUT * KCH];    // 2 x 8192B
    __shared__ __align__(16) __half Bs[2][NTILE * KCH];   // 2 x 8192B  (total 32KB)

    const int tid  = threadIdx.x;
    const int lane = tid & 31;
    const int wid  = tid >> 5;           // 0..7
    const int wm   = wid & 3;            // 32-cout tile
    const int wn   = wid >> 2;           // 64-pixel tile

    const uint32_t sA[2] = { smem_u32(&As[0][0]), smem_u32(&As[1][0]) };
    const uint32_t sB[2] = { smem_u32(&Bs[0][0]), smem_u32(&Bs[1][0]) };

    // ldmatrix per-lane geometry (swizzle term constant per lane: +16*mt/ntp keeps (row>>1)&3)
    const int a_row = wm * 32 + ((lane >> 3) & 1) * 8 + (lane & 7);
    const int a_cb  = lane >> 4;                  // 16B k-subblock 0/1
    const int a_swz = (a_row >> 1) & 3;
    const int b_row = wn * 64 + (lane >> 4) * 8 + (lane & 7);
    const int b_cb  = (lane >> 3) & 1;
    const int b_swz = (b_row >> 1) & 3;

    // geometry
    const int bi = blockIdx.x;
    const int b  = bi / 98;
    const int m0 = (bi - b * 98) * NTILE;
    const float* xb = x + (size_t)b * CIN * NPIX;

    // fill roles: p = pixel (warp-contiguous), kh = channel half (16 ci each)
    const int p  = tid & 127;
    const int kh = tid >> 7;
    const int gpix = m0 + p;
    const int ph = gpix / IMG_W;
    const int pw = gpix - ph * IMG_W;
    unsigned vm = 0;
    #pragma unroll
    for (int rr = 0; rr < 3; ++rr)
        #pragma unroll
        for (int jj = 0; jj < 3; ++jj)
            if ((unsigned)(ph + rr - 1) < (unsigned)IMG_W &&
                (unsigned)(pw + jj - 1) < (unsigned)IMG_W)
                vm |= 1u << (rr * 3 + jj);
    const int bswz = (p >> 1) & 3;
    const float* xpix = xb + gpix;                 // per-thread pixel base

    float c[2][8][4];
    #pragma unroll
    for (int mt = 0; mt < 2; ++mt)
        #pragma unroll
        for (int nt = 0; nt < 8; ++nt)
            #pragma unroll
            for (int i = 0; i < 4; ++i) c[mt][nt][i] = 0.f;

    // B-fill loader: chunk t covers tap rm = t>>1, channels (t&1)*32 + kh*16 + [0,16)
    auto b_load = [&](int t, uint32_t* bpack) {
        const int rm = t >> 1;
        const int dr = rm / 3;
        const int dc = rm - dr * 3;
        const bool valid = (vm >> rm) & 1u;
        const float* bp = xpix + (dr - 1) * IMG_W + (dc - 1)
                        + ((t & 1) * 32 + kh * 16) * NPIX;
        float v[16];
        if (valid) {
            #pragma unroll
            for (int j = 0; j < 16; ++j) v[j] = __ldg(bp + (size_t)j * NPIX);
        } else {
            #pragma unroll
            for (int j = 0; j < 16; ++j) v[j] = 0.f;
        }
        #pragma unroll
        for (int j = 0; j < 8; ++j) {
            __half2 hh = __floats2half2_rn(v[2 * j], v[2 * j + 1]);
            bpack[j] = *(uint32_t*)&hh;
        }
    };
    auto b_store = [&](int buf, uint32_t* bpack) {
        char* rowp = (char*)&Bs[buf][0] + p * ROWB;
        *(uint4*)(rowp + (((kh * 2 + 0) ^ bswz) * 16)) =
            make_uint4(bpack[0], bpack[1], bpack[2], bpack[3]);
        *(uint4*)(rowp + (((kh * 2 + 1) ^ bswz) * 16)) =
            make_uint4(bpack[4], bpack[5], bpack[6], bpack[7]);
    };
    auto a_fill = [&](int t, int buf) {
        const __half* asrc = g_spw2 + (size_t)t * (COUT * KCH) + tid * 16;
        uint32_t adst = sA[buf] + tid * 32;
        cpasync16(adst, asrc);
        cpasync16(adst + 16, asrc + 8);
        asm volatile("cp.async.commit_group;" ::: "memory");
    };

    // ---- prologue: fill buf 0 ----
    {
        a_fill(0, 0);
        uint32_t bpack[8];
        b_load(0, bpack);
        b_store(0, bpack);
        asm volatile("cp.async.wait_group 0;" ::: "memory");
    }
    __syncthreads();

    // ---- mainloop ----
    for (int t = 0; t < NCH; ++t) {
        const int cur = t & 1;
        const int nxt = cur ^ 1;
        const bool hasNext = (t + 1) < NCH;

        uint32_t bpack[8];
        if (hasNext) {
            a_fill(t + 1, nxt);
            b_load(t + 1, bpack);
        }

        // mma: 2 k-steps of 16
        #pragma unroll
        for (int ks = 0; ks < 2; ++ks) {
            uint32_t a[2][4];
            #pragma unroll
            for (int mt = 0; mt < 2; ++mt)
                ldsm_x4(a[mt][0], a[mt][1], a[mt][2], a[mt][3],
                        sA[cur] + (a_row + mt * 16) * ROWB + (((ks * 2 + a_cb) ^ a_swz) * 16));
            #pragma unroll
            for (int ntp = 0; ntp < 4; ++ntp) {
                uint32_t b0, b1, b2, b3;
                ldsm_x4(b0, b1, b2, b3,
                        sB[cur] + (b_row + ntp * 16) * ROWB + (((ks * 2 + b_cb) ^ b_swz) * 16));
                #pragma unroll
                for (int mt = 0; mt < 2; ++mt) {
                    mma16816(c[mt][2 * ntp],     a[mt][0], a[mt][1], a[mt][2], a[mt][3], b0, b1);
                    mma16816(c[mt][2 * ntp + 1], a[mt][0], a[mt][1], a[mt][2], a[mt][3], b2, b3);
                }
            }
        }

        if (hasNext) b_store(nxt, bpack);
        asm volatile("cp.async.wait_group 0;" ::: "memory");
        __syncthreads();
    }

    // ---- epilogue ----
    const int g   = lane >> 2;
    const int tig = lane & 3;
    #pragma unroll
    for (int mt = 0; mt < 2; ++mt) {
        const int r0 = wm * 32 + mt * 16 + g;
        const float bv0 = __ldg(bias + r0);
        const float bv1 = __ldg(bias + r0 + 8);
        float* o0 = out + ((size_t)(b * COUT + r0)) * NPIX + m0;
        float* o1 = out + ((size_t)(b * COUT + r0 + 8)) * NPIX + m0;
        #pragma unroll
        for (int nt = 0; nt < 8; ++nt) {
            const int col = wn * 64 + nt * 8 + tig * 2;
            float2 v0 = { c[mt][nt][0] + bv0, c[mt][nt][1] + bv0 };
            float2 v1 = { c[mt][nt][2] + bv1, c[mt][nt][3] + bv1 };
            *(float2*)(o0 + col) = v0;
            *(float2*)(o1 + col) = v1;
        }
    }
}

extern "C" void kernel_launch(void* const* d_in, const int* in_sizes, int n_in,
                              void* d_out, int out_size) {
    const float* x      = (const float*)d_in[0];
    const float* weight = (const float*)d_in[1];
    const float* mask   = (const float*)d_in[2];
    const float* bias   = (const float*)d_in[3];
    float* out = (float*)d_out;

    spw2_kernel<<<(NCH * COUT * KCH + 255) / 256, 256>>>(weight, mask);
    conv_mma<<<BB * (NPIX / NTILE), 256>>>(x, bias, out);
}